// round 6
// baseline (speedup 1.0000x reference)
#include <cuda_runtime.h>
#include <cuda_bf16.h>

#define Hh 96
#define Ww 96
#define HW (Hh*Ww)
#define NS 8
#define NWORDS (HW/32)   // 288 bitmask words per image

// Per-(sample,direction) directed-distance bits; each slot written by exactly
// one block per launch (atomicExch), so no init pass is needed. d_count is
// zero-initialized at load and reset to 0 by the last block every launch.
__device__ int          d_dirMax[2 * NS];
__device__ unsigned int d_count;

// ---------------------------------------------------------------------------
// Single fused kernel. Block = (direction m, sample n); 16 blocks x 1024 thr.
//   dir 0: sources A\B, target set B;  dir 1: sources B\A, target set A.
// Stage 1: threshold both images -> smem bitmasks (ballot; 18 coalesced
//          global loads per thread = the ONLY global input traffic).
// Stage 2: column EDT of the target mask -> uint16 g2[9216] in smem
//          (96 threads; forward "up" distances packed 4/uint32 in registers).
//          g2 sentinel 65535 = empty column; real values <= 95^2.
// Stage 3: early-exit outward row scan in INTEGER arithmetic:
//          m2 = min_d ( min(g2[j-d],g2[j+d]) + d^2 ), stop when d^2 >= m2.
//          Out-of-range -> 0x7FFFFF. ~2-3 iters for ~50%-dense masks.
// Stage 4: block max reduce -> atomicExch own slot -> counter; last block
//          combines 16 slots into the mean and resets the counter.
// ---------------------------------------------------------------------------
__global__ __launch_bounds__(1024, 1)
void k_hausdorff(const float* __restrict__ predict,
                 const float* __restrict__ target,
                 float* __restrict__ out) {
    const int m = blockIdx.x;          // direction
    const int n = blockIdx.y;          // sample
    const int t = threadIdx.x;

    __shared__ unsigned        mAbits[NWORDS];
    __shared__ unsigned        mBbits[NWORDS];
    __shared__ unsigned short  g2[HW];
    __shared__ float           red[32];

    // ---- Stage 1: threshold + ballot into bitmasks -------------------------
    const float* pa = predict + n * HW;
    const float* pb = target  + n * HW;
    #pragma unroll
    for (int k = 0; k < HW / 1024; k++) {
        int idx = k * 1024 + t;
        // jnp.round(x) > 0.5 for x in [0,1): true iff x > 0.5
        unsigned ba = __ballot_sync(0xffffffffu, pa[idx] > 0.5f);
        unsigned bb = __ballot_sync(0xffffffffu, pb[idx] > 0.5f);
        if ((t & 31) == 0) { mAbits[idx >> 5] = ba; mBbits[idx >> 5] = bb; }
    }
    __syncthreads();

    // ---- Stage 2: column EDT of target mask (threads 0..95) ----------------
    const unsigned* mt = (m == 0) ? mBbits : mAbits;
    if (t < Ww) {
        const int j = t;
        unsigned tmpw[24];
        int up = 127;
        #pragma unroll
        for (int i = 0; i < Hh; i++) {
            int idx = i * Ww + j;
            bool bset = (mt[idx >> 5] >> (idx & 31)) & 1u;
            up = bset ? 0 : ((up < 127) ? up + 1 : 127);
            if ((i & 3) == 0) tmpw[i >> 2] = (unsigned)up;
            else              tmpw[i >> 2] |= ((unsigned)up) << ((i & 3) * 8);
        }
        int down = 127;
        #pragma unroll
        for (int i = Hh - 1; i >= 0; i--) {
            int upv = (int)((tmpw[i >> 2] >> ((i & 3) * 8)) & 255u);
            down = (upv == 0) ? 0 : ((down < 127) ? down + 1 : 127);
            int gm = (upv < down) ? upv : down;
            g2[i * Ww + j] = (gm >= Hh) ? (unsigned short)65535
                                        : (unsigned short)(gm * gm);
        }
    }
    __syncthreads();

    // ---- Stage 3: early-exit row scan, per-thread max ----------------------
    float l = 0.0f;
    #pragma unroll
    for (int k = 0; k < HW / 1024; k++) {
        int idx = k * 1024 + t;
        unsigned wa = (mAbits[idx >> 5] >> (idx & 31)) & 1u;
        unsigned wb = (mBbits[idx >> 5] >> (idx & 31)) & 1u;
        bool src = (m == 0) ? (wa & ~wb) : (wb & ~wa);
        if (src) {
            int i = idx / Ww, j = idx - i * Ww;
            const unsigned short* row = g2 + i * Ww;
            int m2 = row[j];
            #pragma unroll 1
            for (int d = 1; d < Ww; d++) {
                int dd = d * d;
                if (dd >= m2) break;
                int lv = (j - d >= 0) ? (int)row[j - d] : 0x7FFFFF;
                int rv = (j + d < Ww) ? (int)row[j + d] : 0x7FFFFF;
                int c  = (lv < rv ? lv : rv) + dd;
                m2 = (c < m2) ? c : m2;
            }
            // m2 == 65535 exactly <=> target set empty (real dist^2 <= 18050)
            float v = (m2 >= 65535) ? 1e9f : sqrtf((float)m2) * (1.0f / 96.0f);
            l = fmaxf(l, v);
        }
    }

    // ---- Stage 4: block reduce + cross-block combine -----------------------
    #pragma unroll
    for (int off = 16; off > 0; off >>= 1)
        l = fmaxf(l, __shfl_xor_sync(0xffffffffu, l, off));
    if ((t & 31) == 0) red[t >> 5] = l;
    __syncthreads();

    if (t < 32) {
        float v = red[t];
        #pragma unroll
        for (int off = 16; off > 0; off >>= 1)
            v = fmaxf(v, __shfl_xor_sync(0xffffffffu, v, off));
        if (t == 0) {
            // this block is the sole writer of its slot this launch
            atomicExch(&d_dirMax[n * 2 + m], __float_as_int(v));
            __threadfence();
            unsigned done = atomicAdd(&d_count, 1u);
            if (done == 2u * NS - 1u) {
                float acc = 0.0f;
                #pragma unroll
                for (int s = 0; s < NS; s++) {
                    float da = __int_as_float(atomicAdd(&d_dirMax[2 * s + 0], 0));
                    float db = __int_as_float(atomicAdd(&d_dirMax[2 * s + 1], 0));
                    acc += fmaxf(da, db);
                }
                out[0] = acc * (1.0f / (float)NS);
                atomicExch(&d_count, 0u);   // reset for next graph replay
            }
        }
    }
}

extern "C" void kernel_launch(void* const* d_in, const int* in_sizes, int n_in,
                              void* d_out, int out_size) {
    const float* predict = (const float*)d_in[0];
    const float* target  = (const float*)d_in[1];
    float* out = (float*)d_out;

    dim3 grid(2, NS);                 // (direction, sample)
    k_hausdorff<<<grid, 1024>>>(predict, target, out);
}

// round 8
// speedup vs baseline: 1.1830x; 1.1830x over previous
#include <cuda_runtime.h>
#include <cuda_bf16.h>

#define Hh 96
#define Ww 96
#define HW (Hh*Ww)
#define NS 8
#define NWORDS (HW/32)   // 288 row-major bitmask words per image

// Per-(sample,direction) directed-distance bits; each slot written by exactly
// one block per launch (atomicExch) -> no init pass. d_count starts 0 and is
// reset to 0 by the last block each launch (graph-replay deterministic).
__device__ int          d_dirMax[2 * NS];
__device__ unsigned int d_count;

// ---------------------------------------------------------------------------
// Single fused kernel. Block = (direction m, sample n); 16 blocks x 1024 thr.
//   dir 0: sources A\B, target set B;  dir 1: sources B\A, target set A.
// S1: threshold -> row-major bitmasks via ballot (coalesced; only gmem input).
// S2a: transpose TARGET mask into 96-bit column bitsets (9 warps, broadcast
//      LDS reads, no serial recurrence).
// S2b: column EDT per pixel in O(1) with clz/ffs on the column bitset --
//      ALL 1024 threads (the R6 version serialized this on 3 warps).
//      g2 (uint16) sentinel 65535 <=> empty column; real values <= 95^2.
// S3: early-exit outward row scan (integer): m2 = min_d(min(g2[j-d],g2[j+d])+d^2),
//     stop when d^2 >= m2. ~2-3 iters at ~50% density.
// S4: block max reduce -> atomicExch own slot; LAST block combines the 16
//     slots with 16 PARALLEL atomic reads (R6 did 32 serial ones = ~5us tail).
// ---------------------------------------------------------------------------
__global__ __launch_bounds__(1024, 1)
void k_hausdorff(const float* __restrict__ predict,
                 const float* __restrict__ target,
                 float* __restrict__ out) {
    const int m = blockIdx.x;          // direction
    const int n = blockIdx.y;          // sample
    const int t = threadIdx.x;

    __shared__ unsigned       mAbits[NWORDS];
    __shared__ unsigned       mBbits[NWORDS];
    __shared__ unsigned       colbits[Ww * 3];   // target mask, column-major bits
    __shared__ unsigned short g2[HW];
    __shared__ float          red[32];

    // ---- S1: threshold + ballot into row-major bitmasks --------------------
    const float* pa = predict + n * HW;
    const float* pb = target  + n * HW;
    #pragma unroll
    for (int k = 0; k < HW / 1024; k++) {
        int idx = k * 1024 + t;
        // jnp.round(x) > 0.5 for x in [0,1): true iff x > 0.5
        unsigned ba = __ballot_sync(0xffffffffu, pa[idx] > 0.5f);
        unsigned bb = __ballot_sync(0xffffffffu, pb[idx] > 0.5f);
        if ((t & 31) == 0) { mAbits[idx >> 5] = ba; mBbits[idx >> 5] = bb; }
    }
    __syncthreads();

    // ---- S2a: transpose target mask to column bitsets (288 threads) --------
    const unsigned* mt = (m == 0) ? mBbits : mAbits;
    if (t < Ww * 3) {
        int w = t / Ww;                // which 32-row chunk
        int j = t - w * Ww;            // column
        unsigned cw = 0;
        #pragma unroll
        for (int r = 0; r < 32; r++) {
            int i = w * 32 + r;
            cw |= ((mt[i * 3 + (j >> 5)] >> (j & 31)) & 1u) << r;
        }
        colbits[j * 3 + w] = cw;       // stride-3: conflict-free (3 coprime 32)
    }
    __syncthreads();

    // ---- S2b: column EDT per pixel, O(1) via clz/ffs (all threads) ---------
    #pragma unroll
    for (int k = 0; k < HW / 1024; k++) {
        int idx = k * 1024 + t;
        int i = idx / Ww, j = idx - i * Ww;
        unsigned c0 = colbits[j * 3 + 0];
        unsigned c1 = colbits[j * 3 + 1];
        unsigned c2 = colbits[j * 3 + 2];
        int w = i >> 5, b = i & 31;
        unsigned wcur = (w == 0) ? c0 : ((w == 1) ? c1 : c2);
        unsigned wm1  = (w == 0) ? 0u : ((w == 1) ? c0 : c1);
        unsigned wm2  = (w == 2) ? c0 : 0u;
        unsigned wp1  = (w == 0) ? c1 : ((w == 1) ? c2 : 0u);
        unsigned wp2  = (w == 0) ? c2 : 0u;

        // nearest set bit at row <= i
        unsigned x = wcur & (0xffffffffu >> (31 - b));
        int up;
        if (x)        up = b - (31 - __clz(x));
        else if (wm1) up = 32 + b - (31 - __clz(wm1));
        else if (wm2) up = 64 + b - (31 - __clz(wm2));
        else          up = 127;
        // nearest set bit at row >= i
        unsigned y = wcur & (0xffffffffu << b);
        int down;
        if (y)        down = (__ffs(y) - 1) - b;
        else if (wp1) down = 32 - b + (__ffs(wp1) - 1);
        else if (wp2) down = 64 - b + (__ffs(wp2) - 1);
        else          down = 127;

        int g = min(up, down);
        g2[idx] = (g >= Hh) ? (unsigned short)65535 : (unsigned short)(g * g);
    }
    __syncthreads();

    // ---- S3: early-exit row scan, per-thread max ---------------------------
    float l = 0.0f;
    #pragma unroll
    for (int k = 0; k < HW / 1024; k++) {
        int idx = k * 1024 + t;
        unsigned wa = (mAbits[idx >> 5] >> (idx & 31)) & 1u;
        unsigned wb = (mBbits[idx >> 5] >> (idx & 31)) & 1u;
        bool src = (m == 0) ? (wa & ~wb) : (wb & ~wa);
        if (src) {
            int i = idx / Ww, j = idx - i * Ww;
            const unsigned short* row = g2 + i * Ww;
            int m2 = row[j];
            #pragma unroll 1
            for (int d = 1; d < Ww; d++) {
                int dd = d * d;
                if (dd >= m2) break;
                int lv = (j - d >= 0) ? (int)row[j - d] : 0x7FFFFF;
                int rv = (j + d < Ww) ? (int)row[j + d] : 0x7FFFFF;
                m2 = min(m2, min(lv, rv) + dd);
            }
            // m2 == 65535 exactly <=> target set empty (real dist^2 <= 18050)
            float v = (m2 >= 65535) ? 1e9f : sqrtf((float)m2) * (1.0f / 96.0f);
            l = fmaxf(l, v);
        }
    }

    // ---- S4: block reduce + cross-block combine ----------------------------
    #pragma unroll
    for (int off = 16; off > 0; off >>= 1)
        l = fmaxf(l, __shfl_xor_sync(0xffffffffu, l, off));
    if ((t & 31) == 0) red[t >> 5] = l;
    __syncthreads();

    if (t < 32) {
        float v = red[t];
        #pragma unroll
        for (int off = 16; off > 0; off >>= 1)
            v = fmaxf(v, __shfl_xor_sync(0xffffffffu, v, off));

        unsigned lastFlag = 0;
        if (t == 0) {
            // this block is the sole writer of its slot this launch
            atomicExch(&d_dirMax[n * 2 + m], __float_as_int(v));
            __threadfence();
            lastFlag = (atomicAdd(&d_count, 1u) == 2u * NS - 1u) ? 1u : 0u;
        }
        lastFlag = __shfl_sync(0xffffffffu, lastFlag, 0);
        if (lastFlag) {
            __threadfence();                       // acquire side
            float pv = 0.0f;
            if (t < 2 * NS)
                pv = __int_as_float(atomicAdd(&d_dirMax[t], 0));  // 16 parallel
            float other = __shfl_xor_sync(0xffffffffu, pv, 1);
            float pairmax = fmaxf(pv, other);      // max over (dir0, dir1)
            float contrib = ((t & 1) == 0 && t < 2 * NS) ? pairmax : 0.0f;
            #pragma unroll
            for (int off = 16; off > 0; off >>= 1)
                contrib += __shfl_xor_sync(0xffffffffu, contrib, off);
            if (t == 0) {
                out[0] = contrib * (1.0f / (float)NS);
                atomicExch(&d_count, 0u);          // reset for next replay
            }
        }
    }
}

extern "C" void kernel_launch(void* const* d_in, const int* in_sizes, int n_in,
                              void* d_out, int out_size) {
    const float* predict = (const float*)d_in[0];
    const float* target  = (const float*)d_in[1];
    float* out = (float*)d_out;

    dim3 grid(2, NS);                 // (direction, sample)
    k_hausdorff<<<grid, 1024>>>(predict, target, out);
}

// round 10
// speedup vs baseline: 1.3761x; 1.1633x over previous
#include <cuda_runtime.h>
#include <cuda_bf16.h>

#define Hh 96
#define Ww 96
#define HW (Hh*Ww)
#define NS 8
#define NWORDS (HW/32)     // 288 row-major words per image
#define NIMG (2*NS)        // 16 mask images
#define RPB 8              // rows per k_dist block
#define NCHUNK (Hh/RPB)    // 12 row-chunks
#define NBLK (2*NS*NCHUNK) // 192 k_dist blocks

// Inter-kernel scratch (allocation-free, tiny -> L2-resident):
__device__ unsigned     d_rowbits[NIMG][NWORDS];  // row-major mask bits
__device__ unsigned     d_colbits[NIMG][Ww * 3];  // column bitsets [j*3+w]
__device__ int          d_dirMax[NIMG];           // per-(sample,dir) max bits
__device__ unsigned int d_count;                  // starts 0; reset each launch

// ---------------------------------------------------------------------------
// K1: threshold -> ballot row bitmasks -> transpose to column bitsets.
// One block per mask image (16 x 1024). Only consumer of the 1.2MB input.
// Also zeroes d_dirMax (block 0) so K2 can accumulate with atomicMax.
// ---------------------------------------------------------------------------
__global__ __launch_bounds__(1024, 1)
void k_masks(const float* __restrict__ predict,
             const float* __restrict__ target) {
    const int img = blockIdx.x;        // n*2 + m  (m: 0=A/predict, 1=B/target)
    const int t   = threadIdx.x;

    __shared__ unsigned rb[NWORDS];

    const float* p = (((img & 1) == 0) ? predict : target) + (img >> 1) * HW;
    #pragma unroll
    for (int k = 0; k < HW / 1024; k++) {
        int idx = k * 1024 + t;
        // jnp.round(x) > 0.5 for x in [0,1): true iff x > 0.5
        unsigned b = __ballot_sync(0xffffffffu, p[idx] > 0.5f);
        if ((t & 31) == 0) rb[idx >> 5] = b;
    }
    if (img == 0 && t < NIMG) d_dirMax[t] = 0;
    __syncthreads();

    if (t < NWORDS) d_rowbits[img][t] = rb[t];

    if (t < Ww * 3) {                  // transpose: 9 warps, broadcast LDS
        int w = t / Ww;                // 32-row chunk
        int j = t - w * Ww;            // column
        unsigned cw = 0;
        #pragma unroll
        for (int r = 0; r < 32; r++) {
            int i = w * 32 + r;
            cw |= ((rb[i * 3 + (j >> 5)] >> (j & 31)) & 1u) << r;
        }
        d_colbits[img][j * 3 + w] = cw;
    }
}

// ---------------------------------------------------------------------------
// K2: per-pixel directed distance, chip-wide. Block = (dir m, sample n,
// row-chunk rc); 768 threads = 8 rows x 96 cols, one pixel each.
//   dir 0: sources A\B vs target B;  dir 1: sources B\A vs target A.
// Column EDT in O(1) via clz/ffs on the target's column bitset (3 words, L2).
// Row pass: early-exit outward scan over the smem g2 row (integer arith),
// stop when d^2 >= m2. Empty target: g2 sentinel 65535 everywhere -> 1e9.
// Block max reduce -> atomicMax own slot; last of 192 blocks combines the 16
// slots with 16 PARALLEL atomic reads and writes the mean; resets counter.
// ---------------------------------------------------------------------------
__global__ __launch_bounds__(768, 2)
void k_dist(float* __restrict__ out) {
    const int m  = blockIdx.x;
    const int n  = blockIdx.y;
    const int rc = blockIdx.z;
    const int t  = threadIdx.x;
    const int r  = t / Ww;             // 0..7
    const int j  = t - r * Ww;         // 0..95
    const int i  = rc * RPB + r;

    __shared__ unsigned short g2[RPB][Ww];
    __shared__ float red[24];

    const int tgtImg = n * 2 + ((m == 0) ? 1 : 0);

    // ---- column EDT at (i, j) on target mask, O(1) -------------------------
    unsigned c0 = d_colbits[tgtImg][j * 3 + 0];
    unsigned c1 = d_colbits[tgtImg][j * 3 + 1];
    unsigned c2 = d_colbits[tgtImg][j * 3 + 2];
    int w = i >> 5, b = i & 31;
    unsigned wcur = (w == 0) ? c0 : ((w == 1) ? c1 : c2);
    unsigned wm1  = (w == 0) ? 0u : ((w == 1) ? c0 : c1);
    unsigned wm2  = (w == 2) ? c0 : 0u;
    unsigned wp1  = (w == 0) ? c1 : ((w == 1) ? c2 : 0u);
    unsigned wp2  = (w == 0) ? c2 : 0u;

    unsigned x = wcur & (0xffffffffu >> (31 - b));   // bits at rows <= i
    int up;
    if (x)        up = b - (31 - __clz(x));
    else if (wm1) up = 32 + b - (31 - __clz(wm1));
    else if (wm2) up = 64 + b - (31 - __clz(wm2));
    else          up = 127;
    unsigned y = wcur & (0xffffffffu << b);          // bits at rows >= i
    int down;
    if (y)        down = (__ffs(y) - 1) - b;
    else if (wp1) down = 32 - b + (__ffs(wp1) - 1);
    else if (wp2) down = 64 - b + (__ffs(wp2) - 1);
    else          down = 127;

    int g = min(up, down);
    g2[r][j] = (g >= Hh) ? (unsigned short)65535 : (unsigned short)(g * g);

    // ---- source-membership bit --------------------------------------------
    unsigned wa = (d_rowbits[n * 2 + 0][i * 3 + (j >> 5)] >> (j & 31)) & 1u;
    unsigned wb = (d_rowbits[n * 2 + 1][i * 3 + (j >> 5)] >> (j & 31)) & 1u;
    bool src = (m == 0) ? (wa & ~wb) : (wb & ~wa);
    __syncthreads();

    // ---- early-exit row scan ----------------------------------------------
    float l = 0.0f;
    if (src) {
        const unsigned short* row = g2[r];
        int m2 = row[j];
        #pragma unroll 1
        for (int d = 1; d < Ww; d++) {
            int dd = d * d;
            if (dd >= m2) break;
            int lv = (j - d >= 0) ? (int)row[j - d] : 0x7FFFFF;
            int rv = (j + d < Ww) ? (int)row[j + d] : 0x7FFFFF;
            m2 = min(m2, min(lv, rv) + dd);
        }
        // m2 == 65535 exactly <=> empty target (real dist^2 <= 18050)
        l = (m2 >= 65535) ? 1e9f : sqrtf((float)m2) * (1.0f / 96.0f);
    }

    // ---- block reduce + cross-block combine --------------------------------
    #pragma unroll
    for (int off = 16; off > 0; off >>= 1)
        l = fmaxf(l, __shfl_xor_sync(0xffffffffu, l, off));
    if ((t & 31) == 0) red[t >> 5] = l;
    __syncthreads();

    if (t < 32) {
        float v = (t < 24) ? red[t] : 0.0f;
        #pragma unroll
        for (int off = 16; off > 0; off >>= 1)
            v = fmaxf(v, __shfl_xor_sync(0xffffffffu, v, off));

        unsigned lastFlag = 0;
        if (t == 0) {
            // nonnegative floats: int-bit compare preserves order
            atomicMax(&d_dirMax[n * 2 + m], __float_as_int(v));
            __threadfence();
            lastFlag = (atomicAdd(&d_count, 1u) == (unsigned)(NBLK - 1)) ? 1u : 0u;
        }
        lastFlag = __shfl_sync(0xffffffffu, lastFlag, 0);
        if (lastFlag) {
            __threadfence();
            float pv = 0.0f;
            if (t < NIMG)
                pv = __int_as_float(atomicAdd(&d_dirMax[t], 0));  // 16 parallel
            float other   = __shfl_xor_sync(0xffffffffu, pv, 1);
            float pairmax = fmaxf(pv, other);                     // max(dir0,dir1)
            float contrib = ((t & 1) == 0 && t < NIMG) ? pairmax : 0.0f;
            #pragma unroll
            for (int off = 16; off > 0; off >>= 1)
                contrib += __shfl_xor_sync(0xffffffffu, contrib, off);
            if (t == 0) {
                out[0] = contrib * (1.0f / (float)NS);
                atomicExch(&d_count, 0u);         // reset for next replay
            }
        }
    }
}

extern "C" void kernel_launch(void* const* d_in, const int* in_sizes, int n_in,
                              void* d_out, int out_size) {
    const float* predict = (const float*)d_in[0];
    const float* target  = (const float*)d_in[1];
    float* out = (float*)d_out;

    k_masks<<<NIMG, 1024>>>(predict, target);

    dim3 grid(2, NS, NCHUNK);          // (direction, sample, row-chunk)
    k_dist<<<grid, RPB * Ww>>>(out);
}